// round 9
// baseline (speedup 1.0000x reference)
#include <cuda_runtime.h>
#include <math.h>

// Problem constants
#define Bn  4
#define Sn  1024
#define Hn  1280
#define NHn 20
#define DHn 64
#define In  5120
#define Cn  13
#define Pn  8
#define BSn (Bn*Sn)   // 4096

// ---------------- scratch (device globals; allocation-free) ----------------
__device__ __align__(16) float g_R[Pn*Pn];
__device__ __align__(16) float g_ptm[BSn*Pn];
__device__ __align__(16) float g_u[BSn*Pn];
__device__ __align__(16) float g_q[BSn*Hn];
__device__ __align__(16) float g_k[BSn*Hn];
__device__ __align__(16) float g_v[BSn*Hn];
__device__ __align__(16) float g_ctx[BSn*Hn];
__device__ __align__(16) float g_x[BSn*Hn];
__device__ __align__(16) float g_ff[BSn*In];

__device__ __forceinline__ float warp_sum32(float v) {
    #pragma unroll
    for (int o = 16; o; o >>= 1) v += __shfl_xor_sync(0xffffffffu, v, o);
    return v;
}

// ---------------- R = out1 @ out2 (8x8) ----------------
__global__ void compute_R_kernel(const float* __restrict__ W1, const float* __restrict__ b1,
                                 const float* __restrict__ W2, const float* __restrict__ b2,
                                 const float* __restrict__ M) {
    int p = threadIdx.x >> 3;
    int q = threadIdx.x & 7;
    if (threadIdx.x >= 64) return;
    float acc = 0.f;
    for (int c = 0; c < Cn; c++) {
        float o1 = b1[p];
        #pragma unroll
        for (int cc = 0; cc < Cn; cc++) o1 += M[cc*Cn + c] * W1[p*Cn + cc];
        float o2 = b2[q];
        #pragma unroll
        for (int dd = 0; dd < Cn; dd++) o2 += M[c*Cn + dd] * W2[q*Cn + dd];
        acc += o1 * o2;
    }
    g_R[p*Pn + q] = acc;
}

// ---------------- ptm = softmax(h @ Wptm^T + b), u = ptm @ R ----------------
__global__ void ptm_kernel(const float* __restrict__ h, const float* __restrict__ Wp,
                           const float* __restrict__ bp) {
    __shared__ float hs[Hn];
    __shared__ float logits[Pn];
    int row = blockIdx.x;
    int t = threadIdx.x;
    for (int k = t; k < Hn; k += 256) hs[k] = h[(size_t)row*Hn + k];
    __syncthreads();
    int w = t >> 5, lane = t & 31;
    float s = 0.f;
    for (int k = lane; k < Hn; k += 32) s += hs[k] * Wp[w*Hn + k];
    s = warp_sum32(s);
    if (lane == 0) logits[w] = s + bp[w];
    __syncthreads();
    if (t == 0) {
        float mx = -3.4e38f;
        #pragma unroll
        for (int p = 0; p < Pn; p++) mx = fmaxf(mx, logits[p]);
        float e[Pn], sum = 0.f;
        #pragma unroll
        for (int p = 0; p < Pn; p++) { e[p] = __expf(logits[p] - mx); sum += e[p]; }
        float inv = 1.f / sum;
        float pt[Pn];
        #pragma unroll
        for (int p = 0; p < Pn; p++) { pt[p] = e[p]*inv; g_ptm[row*Pn + p] = pt[p]; }
        #pragma unroll
        for (int d = 0; d < Pn; d++) {
            float uu = 0.f;
            #pragma unroll
            for (int c = 0; c < Cn && c < Pn; c++) uu += pt[c] * g_R[c*Pn + d];
            g_u[row*Pn + d] = uu;
        }
    }
}

// ---------------- tiled SGEMM: C[i,j] = sum_k A[i,k]*W[j,k] + bias[j] ----------------
// epi: 0 none, 1 exact GELU, 2 add residual res[i,j]
__global__ __launch_bounds__(256, 2)
void gemm_nt(const float* __restrict__ A, const float* __restrict__ W,
             const float* __restrict__ bias, const float* __restrict__ res,
             float* __restrict__ C, int Nc, int Kd, int epi) {
    __shared__ float As[16][128];
    __shared__ float Bs[16][128];
    int t  = threadIdx.x;
    int tx = t & 15, ty = t >> 4;
    int row0 = blockIdx.y * 128;
    int col0 = blockIdx.x * 128;
    const float* Ab = A + (size_t)row0 * Kd;
    const float* Wb = W + (size_t)col0 * Kd;
    float acc[8][8];
    #pragma unroll
    for (int i = 0; i < 8; i++)
        #pragma unroll
        for (int j = 0; j < 8; j++) acc[i][j] = 0.f;

    for (int k0 = 0; k0 < Kd; k0 += 16) {
        #pragma unroll
        for (int i = 0; i < 2; i++) {
            int idx = i*256 + t;
            int r  = idx >> 2;
            int kc = (idx & 3) * 4;
            float4 va = *(const float4*)(Ab + (size_t)r*Kd + k0 + kc);
            As[kc+0][r] = va.x; As[kc+1][r] = va.y; As[kc+2][r] = va.z; As[kc+3][r] = va.w;
            float4 vb = *(const float4*)(Wb + (size_t)r*Kd + k0 + kc);
            Bs[kc+0][r] = vb.x; Bs[kc+1][r] = vb.y; Bs[kc+2][r] = vb.z; Bs[kc+3][r] = vb.w;
        }
        __syncthreads();
        #pragma unroll
        for (int k = 0; k < 16; k++) {
            float4 a0 = *(const float4*)&As[k][ty*4];
            float4 a1 = *(const float4*)&As[k][64 + ty*4];
            float4 b0 = *(const float4*)&Bs[k][tx*4];
            float4 b1 = *(const float4*)&Bs[k][64 + tx*4];
            float a[8] = {a0.x,a0.y,a0.z,a0.w,a1.x,a1.y,a1.z,a1.w};
            float b[8] = {b0.x,b0.y,b0.z,b0.w,b1.x,b1.y,b1.z,b1.w};
            #pragma unroll
            for (int i = 0; i < 8; i++)
                #pragma unroll
                for (int j = 0; j < 8; j++)
                    acc[i][j] = fmaf(a[i], b[j], acc[i][j]);
        }
        __syncthreads();
    }
    #pragma unroll
    for (int i = 0; i < 8; i++) {
        int r = row0 + ((i < 4) ? (ty*4 + i) : (64 + ty*4 + i - 4));
        #pragma unroll
        for (int j = 0; j < 8; j++) {
            int c = col0 + ((j < 4) ? (tx*4 + j) : (64 + tx*4 + j - 4));
            float v = acc[i][j] + bias[c];
            if (epi == 1) {
                v = 0.5f * v * (1.f + erff(v * 0.70710678118654752f));
            } else if (epi == 2) {
                v += res[(size_t)r*Nc + c];
            }
            C[(size_t)r*Nc + c] = v;
        }
    }
}

// ---------------- flash attention with fused rank-8 tanh bias ----------------
// grid (S/64, NH, B), 256 threads (tx 0..15, ty 0..15); each thread: 4x4 tiles
__global__ void attn_kernel(const float* __restrict__ mask,
                            const float* __restrict__ bscale_p) {
    extern __shared__ float sm[];
    float* Qs  = sm;                 // [64 d][65]  transposed, stride 65
    float* Ks  = Qs  + 64*65;        // [64 d][65]
    float* Ps  = Ks  + 64*65;        // [64 j][65]  probs transposed
    float* Vs  = Ps  + 64*65;        // [64 j][64]  natural
    float* us  = Vs  + 64*64;        // [64 r][8]
    float* pts = us  + 64*8;         // [64 c][8]
    float* msk = pts + 64*8;         // [64]

    int b  = blockIdx.z, hh = blockIdx.y;
    int q0 = blockIdx.x * 64;
    int t  = threadIdx.x;
    int tx = t & 15, ty = t >> 4;
    float bscale = bscale_p[0];

    // load Q tile (transposed) and u rows
    #pragma unroll
    for (int i = 0; i < 4; i++) {
        int idx = i*256 + t;
        int r = idx >> 4, dc = (idx & 15) * 4;
        float4 v = *(const float4*)(g_q + ((size_t)(b*Sn + q0 + r))*Hn + hh*DHn + dc);
        Qs[(dc+0)*65 + r] = v.x; Qs[(dc+1)*65 + r] = v.y;
        Qs[(dc+2)*65 + r] = v.z; Qs[(dc+3)*65 + r] = v.w;
    }
    if (t < 128) {
        int r = t >> 1, c = (t & 1) * 4;
        *(float4*)(us + r*8 + c) = *(const float4*)(g_u + ((size_t)(b*Sn + q0 + r))*Pn + c);
    }

    float m_i[4], l_i[4], o[4][4];
    #pragma unroll
    for (int i = 0; i < 4; i++) {
        m_i[i] = -3.4028235e38f; l_i[i] = 0.f;
        #pragma unroll
        for (int j = 0; j < 4; j++) o[i][j] = 0.f;
    }
    __syncthreads();

    for (int m0 = 0; m0 < Sn; m0 += 64) {
        // load K (transposed), V (natural), ptm cols, mask terms
        #pragma unroll
        for (int i = 0; i < 4; i++) {
            int idx = i*256 + t;
            int r = idx >> 4, dc = (idx & 15) * 4;
            size_t base = ((size_t)(b*Sn + m0 + r))*Hn + hh*DHn + dc;
            float4 kv = *(const float4*)(g_k + base);
            Ks[(dc+0)*65 + r] = kv.x; Ks[(dc+1)*65 + r] = kv.y;
            Ks[(dc+2)*65 + r] = kv.z; Ks[(dc+3)*65 + r] = kv.w;
            *(float4*)(Vs + r*64 + dc) = *(const float4*)(g_v + base);
        }
        if (t < 128) {
            int r = t >> 1, c = (t & 1) * 4;
            *(float4*)(pts + r*8 + c) = *(const float4*)(g_ptm + ((size_t)(b*Sn + m0 + r))*Pn + c);
        }
        if (t < 64) msk[t] = (1.0f - mask[b*Sn + m0 + t]) * (-3.4028235e38f);
        __syncthreads();

        // S = Q K^T
        float s[4][4];
        #pragma unroll
        for (int i = 0; i < 4; i++)
            #pragma unroll
            for (int j = 0; j < 4; j++) s[i][j] = 0.f;
        #pragma unroll 8
        for (int d = 0; d < 64; d++) {
            float a[4], bb[4];
            #pragma unroll
            for (int i = 0; i < 4; i++) a[i]  = Qs[d*65 + ty*4 + i];
            #pragma unroll
            for (int j = 0; j < 4; j++) bb[j] = Ks[d*65 + tx*4 + j];
            #pragma unroll
            for (int i = 0; i < 4; i++)
                #pragma unroll
                for (int j = 0; j < 4; j++)
                    s[i][j] = fmaf(a[i], bb[j], s[i][j]);
        }
        // scale + tanh bias + mask
        #pragma unroll
        for (int i = 0; i < 4; i++) {
            #pragma unroll
            for (int j = 0; j < 4; j++) {
                float dot = 0.f;
                #pragma unroll
                for (int c = 0; c < Pn; c++)
                    dot += us[(ty*4 + i)*8 + c] * pts[(tx*4 + j)*8 + c];
                s[i][j] = s[i][j]*0.125f + tanhf(dot)*bscale + msk[tx*4 + j];
            }
        }
        // online softmax (rows shared by 16 tx lanes within a 16-lane group)
        #pragma unroll
        for (int i = 0; i < 4; i++) {
            float mx = fmaxf(fmaxf(s[i][0], s[i][1]), fmaxf(s[i][2], s[i][3]));
            #pragma unroll
            for (int off = 8; off; off >>= 1)
                mx = fmaxf(mx, __shfl_xor_sync(0xffffffffu, mx, off));
            float mnew = fmaxf(m_i[i], mx);
            float f = __expf(m_i[i] - mnew);
            float rs = 0.f;
            #pragma unroll
            for (int j = 0; j < 4; j++) { s[i][j] = __expf(s[i][j] - mnew); rs += s[i][j]; }
            #pragma unroll
            for (int off = 8; off; off >>= 1)
                rs += __shfl_xor_sync(0xffffffffu, rs, off);
            l_i[i] = l_i[i]*f + rs;
            m_i[i] = mnew;
            #pragma unroll
            for (int j = 0; j < 4; j++) o[i][j] *= f;
        }
        // stash P transposed
        #pragma unroll
        for (int i = 0; i < 4; i++)
            #pragma unroll
            for (int j = 0; j < 4; j++)
                Ps[(tx*4 + j)*65 + ty*4 + i] = s[i][j];
        __syncthreads();
        // O += P V
        #pragma unroll 4
        for (int j = 0; j < 64; j++) {
            float p_[4];
            #pragma unroll
            for (int i = 0; i < 4; i++) p_[i] = Ps[j*65 + ty*4 + i];
            float4 vv = *(const float4*)(Vs + j*64 + tx*4);
            float vb[4] = {vv.x, vv.y, vv.z, vv.w};
            #pragma unroll
            for (int i = 0; i < 4; i++)
                #pragma unroll
                for (int c = 0; c < 4; c++)
                    o[i][c] = fmaf(p_[i], vb[c], o[i][c]);
        }
        __syncthreads();
    }

    #pragma unroll
    for (int i = 0; i < 4; i++) {
        float inv = 1.f / l_i[i];
        int r = q0 + ty*4 + i;
        #pragma unroll
        for (int c = 0; c < 4; c++) {
            int dh = tx*4 + c;
            g_ctx[((size_t)(b*Sn + r))*Hn + hh*DHn + dh] = o[i][c] * inv;
        }
    }
}

// ---------------- residual + LayerNorm ----------------
__global__ void ln_kernel(const float* __restrict__ h,
                          const float* __restrict__ gam, const float* __restrict__ bet) {
    int row = blockIdx.x;
    int t = threadIdx.x;
    float v[5];
    float sum = 0.f, sq = 0.f;
    #pragma unroll
    for (int i = 0; i < 5; i++) {
        int k = t + i*256;
        float a = h[(size_t)row*Hn + k] + g_ctx[(size_t)row*Hn + k];
        v[i] = a; sum += a; sq += a*a;
    }
    __shared__ float s1[8], s2[8];
    sum = warp_sum32(sum); sq = warp_sum32(sq);
    int w = t >> 5, lane = t & 31;
    if (lane == 0) { s1[w] = sum; s2[w] = sq; }
    __syncthreads();
    if (t == 0) {
        float a = 0.f, bq = 0.f;
        #pragma unroll
        for (int i = 0; i < 8; i++) { a += s1[i]; bq += s2[i]; }
        s1[0] = a; s2[0] = bq;
    }
    __syncthreads();
    float mean = s1[0] * (1.f/Hn);
    float var  = s2[0] * (1.f/Hn) - mean*mean;
    float rstd = rsqrtf(var + 1e-5f);
    #pragma unroll
    for (int i = 0; i < 5; i++) {
        int k = t + i*256;
        g_x[(size_t)row*Hn + k] = (v[i] - mean) * rstd * gam[k] + bet[k];
    }
}

// ---------------- launcher ----------------
extern "C" void kernel_launch(void* const* d_in, const int* in_sizes, int n_in,
                              void* d_out, int out_size) {
    const float* h      = (const float*)d_in[0];
    const float* amask  = (const float*)d_in[1];
    const float* Wq     = (const float*)d_in[2];
    const float* bq     = (const float*)d_in[3];
    const float* Wk     = (const float*)d_in[4];
    const float* bk     = (const float*)d_in[5];
    const float* Wv     = (const float*)d_in[6];
    const float* bv     = (const float*)d_in[7];
    const float* W_ct1  = (const float*)d_in[8];
    const float* b_ct1  = (const float*)d_in[9];
    const float* W_ct2  = (const float*)d_in[10];
    const float* b_ct2  = (const float*)d_in[11];
    const float* Mm     = (const float*)d_in[12];
    const float* bscale = (const float*)d_in[13];
    const float* W_ptm  = (const float*)d_in[14];
    const float* b_ptm  = (const float*)d_in[15];
    const float* ln_g   = (const float*)d_in[16];
    const float* ln_b   = (const float*)d_in[17];
    const float* Wf1    = (const float*)d_in[18];
    const float* bf1    = (const float*)d_in[19];
    const float* Wf2    = (const float*)d_in[20];
    const float* bf2    = (const float*)d_in[21];
    float* out = (float*)d_out;

    float *p_q, *p_k, *p_v, *p_x, *p_ff;
    cudaGetSymbolAddress((void**)&p_q,  g_q);
    cudaGetSymbolAddress((void**)&p_k,  g_k);
    cudaGetSymbolAddress((void**)&p_v,  g_v);
    cudaGetSymbolAddress((void**)&p_x,  g_x);
    cudaGetSymbolAddress((void**)&p_ff, g_ff);

    // 1) R (8x8)
    compute_R_kernel<<<1, 64>>>(W_ct1, b_ct1, W_ct2, b_ct2, Mm);
    // 2) ptm + u
    ptm_kernel<<<BSn, 256>>>(h, W_ptm, b_ptm);
    // 3) QKV projections
    dim3 gqkv(Hn/128, BSn/128);
    gemm_nt<<<gqkv, 256>>>(h, Wq, bq, nullptr, p_q, Hn, Hn, 0);
    gemm_nt<<<gqkv, 256>>>(h, Wk, bk, nullptr, p_k, Hn, Hn, 0);
    gemm_nt<<<gqkv, 256>>>(h, Wv, bv, nullptr, p_v, Hn, Hn, 0);
    // 4) attention (flash, fused bias)
    size_t smem = (size_t)(3*64*65 + 64*64 + 64*8 + 64*8 + 64) * sizeof(float);
    cudaFuncSetAttribute(attn_kernel, cudaFuncAttributeMaxDynamicSharedMemorySize, (int)smem);
    attn_kernel<<<dim3(Sn/64, NHn, Bn), 256, smem>>>(amask, bscale);
    // 5) residual + LN
    ln_kernel<<<BSn, 256>>>(h, ln_g, ln_b);
    // 6) FFN1 + GELU
    gemm_nt<<<dim3(In/128, BSn/128), 256>>>(p_x, Wf1, bf1, nullptr, p_ff, In, Hn, 1);
    // 7) FFN2 + residual -> out
    gemm_nt<<<dim3(Hn/128, BSn/128), 256>>>(p_ff, Wf2, bf2, p_x, out, Hn, In, 2);
}

// round 10
// speedup vs baseline: 1.0012x; 1.0012x over previous
#include <cuda_runtime.h>
#include <math.h>

// Problem constants
#define Bn  4
#define Sn  1024
#define Hn  1280
#define NHn 20
#define DHn 64
#define In  5120
#define Cn  13
#define Pn  8
#define BSn (Bn*Sn)   // 4096

// ---------------- scratch (device globals; allocation-free) ----------------
__device__ __align__(16) float g_R[Pn*Pn];
__device__ __align__(16) float g_ptm[BSn*Pn];
__device__ __align__(16) float g_u[BSn*Pn];
__device__ __align__(16) float g_q[BSn*Hn];
__device__ __align__(16) float g_k[BSn*Hn];
__device__ __align__(16) float g_v[BSn*Hn];
__device__ __align__(16) float g_ctx[BSn*Hn];
__device__ __align__(16) float g_x[BSn*Hn];
__device__ __align__(16) float g_ff[BSn*In];

__device__ __forceinline__ float warp_sum32(float v) {
    #pragma unroll
    for (int o = 16; o; o >>= 1) v += __shfl_xor_sync(0xffffffffu, v, o);
    return v;
}

// ---------------- R = out1 @ out2 (8x8) ----------------
__global__ void compute_R_kernel(const float* __restrict__ W1, const float* __restrict__ b1,
                                 const float* __restrict__ W2, const float* __restrict__ b2,
                                 const float* __restrict__ M) {
    int p = threadIdx.x >> 3;
    int q = threadIdx.x & 7;
    if (threadIdx.x >= 64) return;
    float acc = 0.f;
    for (int c = 0; c < Cn; c++) {
        float o1 = b1[p];
        #pragma unroll
        for (int cc = 0; cc < Cn; cc++) o1 += M[cc*Cn + c] * W1[p*Cn + cc];
        float o2 = b2[q];
        #pragma unroll
        for (int dd = 0; dd < Cn; dd++) o2 += M[c*Cn + dd] * W2[q*Cn + dd];
        acc += o1 * o2;
    }
    g_R[p*Pn + q] = acc;
}

// ---------------- ptm = softmax(h @ Wptm^T + b), u = ptm @ R ----------------
__global__ void ptm_kernel(const float* __restrict__ h, const float* __restrict__ Wp,
                           const float* __restrict__ bp) {
    __shared__ float hs[Hn];
    __shared__ float logits[Pn];
    int row = blockIdx.x;
    int t = threadIdx.x;
    for (int k = t; k < Hn; k += 256) hs[k] = h[(size_t)row*Hn + k];
    __syncthreads();
    int w = t >> 5, lane = t & 31;
    float s = 0.f;
    for (int k = lane; k < Hn; k += 32) s += hs[k] * Wp[w*Hn + k];
    s = warp_sum32(s);
    if (lane == 0) logits[w] = s + bp[w];
    __syncthreads();
    if (t == 0) {
        float mx = -3.4e38f;
        #pragma unroll
        for (int p = 0; p < Pn; p++) mx = fmaxf(mx, logits[p]);
        float e[Pn], sum = 0.f;
        #pragma unroll
        for (int p = 0; p < Pn; p++) { e[p] = __expf(logits[p] - mx); sum += e[p]; }
        float inv = 1.f / sum;
        float pt[Pn];
        #pragma unroll
        for (int p = 0; p < Pn; p++) { pt[p] = e[p]*inv; g_ptm[row*Pn + p] = pt[p]; }
        #pragma unroll
        for (int d = 0; d < Pn; d++) {
            float uu = 0.f;
            #pragma unroll
            for (int c = 0; c < Cn && c < Pn; c++) uu += pt[c] * g_R[c*Pn + d];
            g_u[row*Pn + d] = uu;
        }
    }
}

// ---------------- tiled SGEMM: C[i,j] = sum_k A[i,k]*W[j,k] + bias[j] ----------------
// epi: 0 none, 1 exact GELU, 2 add residual res[i,j]
__global__ __launch_bounds__(256, 2)
void gemm_nt(const float* __restrict__ A, const float* __restrict__ W,
             const float* __restrict__ bias, const float* __restrict__ res,
             float* __restrict__ C, int Nc, int Kd, int epi) {
    __shared__ float As[16][128];
    __shared__ float Bs[16][128];
    int t  = threadIdx.x;
    int tx = t & 15, ty = t >> 4;
    int row0 = blockIdx.y * 128;
    int col0 = blockIdx.x * 128;
    const float* Ab = A + (size_t)row0 * Kd;
    const float* Wb = W + (size_t)col0 * Kd;
    float acc[8][8];
    #pragma unroll
    for (int i = 0; i < 8; i++)
        #pragma unroll
        for (int j = 0; j < 8; j++) acc[i][j] = 0.f;

    for (int k0 = 0; k0 < Kd; k0 += 16) {
        #pragma unroll
        for (int i = 0; i < 2; i++) {
            int idx = i*256 + t;
            int r  = idx >> 2;
            int kc = (idx & 3) * 4;
            float4 va = *(const float4*)(Ab + (size_t)r*Kd + k0 + kc);
            As[kc+0][r] = va.x; As[kc+1][r] = va.y; As[kc+2][r] = va.z; As[kc+3][r] = va.w;
            float4 vb = *(const float4*)(Wb + (size_t)r*Kd + k0 + kc);
            Bs[kc+0][r] = vb.x; Bs[kc+1][r] = vb.y; Bs[kc+2][r] = vb.z; Bs[kc+3][r] = vb.w;
        }
        __syncthreads();
        #pragma unroll
        for (int k = 0; k < 16; k++) {
            float4 a0 = *(const float4*)&As[k][ty*4];
            float4 a1 = *(const float4*)&As[k][64 + ty*4];
            float4 b0 = *(const float4*)&Bs[k][tx*4];
            float4 b1 = *(const float4*)&Bs[k][64 + tx*4];
            float a[8] = {a0.x,a0.y,a0.z,a0.w,a1.x,a1.y,a1.z,a1.w};
            float b[8] = {b0.x,b0.y,b0.z,b0.w,b1.x,b1.y,b1.z,b1.w};
            #pragma unroll
            for (int i = 0; i < 8; i++)
                #pragma unroll
                for (int j = 0; j < 8; j++)
                    acc[i][j] = fmaf(a[i], b[j], acc[i][j]);
        }
        __syncthreads();
    }
    #pragma unroll
    for (int i = 0; i < 8; i++) {
        int r = row0 + ((i < 4) ? (ty*4 + i) : (64 + ty*4 + i - 4));
        #pragma unroll
        for (int j = 0; j < 8; j++) {
            int c = col0 + ((j < 4) ? (tx*4 + j) : (64 + tx*4 + j - 4));
            float v = acc[i][j] + bias[c];
            if (epi == 1) {
                v = 0.5f * v * (1.f + erff(v * 0.70710678118654752f));
            } else if (epi == 2) {
                v += res[(size_t)r*Nc + c];
            }
            C[(size_t)r*Nc + c] = v;
        }
    }
}

// ---------------- flash attention with fused rank-8 tanh bias ----------------
// grid (S/64, NH, B), 256 threads (tx 0..15, ty 0..15); each thread: 4x4 tiles
__global__ void attn_kernel(const float* __restrict__ mask,
                            const float* __restrict__ bscale_p) {
    extern __shared__ float sm[];
    float* Qs  = sm;                 // [64 d][65]  transposed, stride 65
    float* Ks  = Qs  + 64*65;        // [64 d][65]
    float* Ps  = Ks  + 64*65;        // [64 j][65]  probs transposed
    float* Vs  = Ps  + 64*65;        // [64 j][64]  natural
    float* us  = Vs  + 64*64;        // [64 r][8]
    float* pts = us  + 64*8;         // [64 c][8]
    float* msk = pts + 64*8;         // [64]

    int b  = blockIdx.z, hh = blockIdx.y;
    int q0 = blockIdx.x * 64;
    int t  = threadIdx.x;
    int tx = t & 15, ty = t >> 4;
    float bscale = bscale_p[0];

    // load Q tile (transposed) and u rows
    #pragma unroll
    for (int i = 0; i < 4; i++) {
        int idx = i*256 + t;
        int r = idx >> 4, dc = (idx & 15) * 4;
        float4 v = *(const float4*)(g_q + ((size_t)(b*Sn + q0 + r))*Hn + hh*DHn + dc);
        Qs[(dc+0)*65 + r] = v.x; Qs[(dc+1)*65 + r] = v.y;
        Qs[(dc+2)*65 + r] = v.z; Qs[(dc+3)*65 + r] = v.w;
    }
    if (t < 128) {
        int r = t >> 1, c = (t & 1) * 4;
        *(float4*)(us + r*8 + c) = *(const float4*)(g_u + ((size_t)(b*Sn + q0 + r))*Pn + c);
    }

    float m_i[4], l_i[4], o[4][4];
    #pragma unroll
    for (int i = 0; i < 4; i++) {
        m_i[i] = -3.4028235e38f; l_i[i] = 0.f;
        #pragma unroll
        for (int j = 0; j < 4; j++) o[i][j] = 0.f;
    }
    __syncthreads();

    for (int m0 = 0; m0 < Sn; m0 += 64) {
        // load K (transposed), V (natural), ptm cols, mask terms
        #pragma unroll
        for (int i = 0; i < 4; i++) {
            int idx = i*256 + t;
            int r = idx >> 4, dc = (idx & 15) * 4;
            size_t base = ((size_t)(b*Sn + m0 + r))*Hn + hh*DHn + dc;
            float4 kv = *(const float4*)(g_k + base);
            Ks[(dc+0)*65 + r] = kv.x; Ks[(dc+1)*65 + r] = kv.y;
            Ks[(dc+2)*65 + r] = kv.z; Ks[(dc+3)*65 + r] = kv.w;
            *(float4*)(Vs + r*64 + dc) = *(const float4*)(g_v + base);
        }
        if (t < 128) {
            int r = t >> 1, c = (t & 1) * 4;
            *(float4*)(pts + r*8 + c) = *(const float4*)(g_ptm + ((size_t)(b*Sn + m0 + r))*Pn + c);
        }
        if (t < 64) msk[t] = (1.0f - mask[b*Sn + m0 + t]) * (-3.4028235e38f);
        __syncthreads();

        // S = Q K^T
        float s[4][4];
        #pragma unroll
        for (int i = 0; i < 4; i++)
            #pragma unroll
            for (int j = 0; j < 4; j++) s[i][j] = 0.f;
        #pragma unroll 8
        for (int d = 0; d < 64; d++) {
            float a[4], bb[4];
            #pragma unroll
            for (int i = 0; i < 4; i++) a[i]  = Qs[d*65 + ty*4 + i];
            #pragma unroll
            for (int j = 0; j < 4; j++) bb[j] = Ks[d*65 + tx*4 + j];
            #pragma unroll
            for (int i = 0; i < 4; i++)
                #pragma unroll
                for (int j = 0; j < 4; j++)
                    s[i][j] = fmaf(a[i], bb[j], s[i][j]);
        }
        // scale + tanh bias + mask
        #pragma unroll
        for (int i = 0; i < 4; i++) {
            #pragma unroll
            for (int j = 0; j < 4; j++) {
                float dot = 0.f;
                #pragma unroll
                for (int c = 0; c < Pn; c++)
                    dot += us[(ty*4 + i)*8 + c] * pts[(tx*4 + j)*8 + c];
                s[i][j] = s[i][j]*0.125f + tanhf(dot)*bscale + msk[tx*4 + j];
            }
        }
        // online softmax (rows shared by 16 tx lanes within a 16-lane group)
        #pragma unroll
        for (int i = 0; i < 4; i++) {
            float mx = fmaxf(fmaxf(s[i][0], s[i][1]), fmaxf(s[i][2], s[i][3]));
            #pragma unroll
            for (int off = 8; off; off >>= 1)
                mx = fmaxf(mx, __shfl_xor_sync(0xffffffffu, mx, off));
            float mnew = fmaxf(m_i[i], mx);
            float f = __expf(m_i[i] - mnew);
            float rs = 0.f;
            #pragma unroll
            for (int j = 0; j < 4; j++) { s[i][j] = __expf(s[i][j] - mnew); rs += s[i][j]; }
            #pragma unroll
            for (int off = 8; off; off >>= 1)
                rs += __shfl_xor_sync(0xffffffffu, rs, off);
            l_i[i] = l_i[i]*f + rs;
            m_i[i] = mnew;
            #pragma unroll
            for (int j = 0; j < 4; j++) o[i][j] *= f;
        }
        // stash P transposed
        #pragma unroll
        for (int i = 0; i < 4; i++)
            #pragma unroll
            for (int j = 0; j < 4; j++)
                Ps[(tx*4 + j)*65 + ty*4 + i] = s[i][j];
        __syncthreads();
        // O += P V
        #pragma unroll 4
        for (int j = 0; j < 64; j++) {
            float p_[4];
            #pragma unroll
            for (int i = 0; i < 4; i++) p_[i] = Ps[j*65 + ty*4 + i];
            float4 vv = *(const float4*)(Vs + j*64 + tx*4);
            float vb[4] = {vv.x, vv.y, vv.z, vv.w};
            #pragma unroll
            for (int i = 0; i < 4; i++)
                #pragma unroll
                for (int c = 0; c < 4; c++)
                    o[i][c] = fmaf(p_[i], vb[c], o[i][c]);
        }
        __syncthreads();
    }

    #pragma unroll
    for (int i = 0; i < 4; i++) {
        float inv = 1.f / l_i[i];
        int r = q0 + ty*4 + i;
        #pragma unroll
        for (int c = 0; c < 4; c++) {
            int dh = tx*4 + c;
            g_ctx[((size_t)(b*Sn + r))*Hn + hh*DHn + dh] = o[i][c] * inv;
        }
    }
}

// ---------------- residual + LayerNorm ----------------
__global__ void ln_kernel(const float* __restrict__ h,
                          const float* __restrict__ gam, const float* __restrict__ bet) {
    int row = blockIdx.x;
    int t = threadIdx.x;
    float v[5];
    float sum = 0.f, sq = 0.f;
    #pragma unroll
    for (int i = 0; i < 5; i++) {
        int k = t + i*256;
        float a = h[(size_t)row*Hn + k] + g_ctx[(size_t)row*Hn + k];
        v[i] = a; sum += a; sq += a*a;
    }
    __shared__ float s1[8], s2[8];
    sum = warp_sum32(sum); sq = warp_sum32(sq);
    int w = t >> 5, lane = t & 31;
    if (lane == 0) { s1[w] = sum; s2[w] = sq; }
    __syncthreads();
    if (t == 0) {
        float a = 0.f, bq = 0.f;
        #pragma unroll
        for (int i = 0; i < 8; i++) { a += s1[i]; bq += s2[i]; }
        s1[0] = a; s2[0] = bq;
    }
    __syncthreads();
    float mean = s1[0] * (1.f/Hn);
    float var  = s2[0] * (1.f/Hn) - mean*mean;
    float rstd = rsqrtf(var + 1e-5f);
    #pragma unroll
    for (int i = 0; i < 5; i++) {
        int k = t + i*256;
        g_x[(size_t)row*Hn + k] = (v[i] - mean) * rstd * gam[k] + bet[k];
    }
}

// ---------------- launcher ----------------
extern "C" void kernel_launch(void* const* d_in, const int* in_sizes, int n_in,
                              void* d_out, int out_size) {
    const float* h      = (const float*)d_in[0];
    const float* amask  = (const float*)d_in[1];
    const float* Wq     = (const float*)d_in[2];
    const float* bq     = (const float*)d_in[3];
    const float* Wk     = (const float*)d_in[4];
    const float* bk     = (const float*)d_in[5];
    const float* Wv     = (const float*)d_in[6];
    const float* bv     = (const float*)d_in[7];
    const float* W_ct1  = (const float*)d_in[8];
    const float* b_ct1  = (const float*)d_in[9];
    const float* W_ct2  = (const float*)d_in[10];
    const float* b_ct2  = (const float*)d_in[11];
    const float* Mm     = (const float*)d_in[12];
    const float* bscale = (const float*)d_in[13];
    const float* W_ptm  = (const float*)d_in[14];
    const float* b_ptm  = (const float*)d_in[15];
    const float* ln_g   = (const float*)d_in[16];
    const float* ln_b   = (const float*)d_in[17];
    const float* Wf1    = (const float*)d_in[18];
    const float* bf1    = (const float*)d_in[19];
    const float* Wf2    = (const float*)d_in[20];
    const float* bf2    = (const float*)d_in[21];
    float* out = (float*)d_out;

    float *p_q, *p_k, *p_v, *p_x, *p_ff;
    cudaGetSymbolAddress((void**)&p_q,  g_q);
    cudaGetSymbolAddress((void**)&p_k,  g_k);
    cudaGetSymbolAddress((void**)&p_v,  g_v);
    cudaGetSymbolAddress((void**)&p_x,  g_x);
    cudaGetSymbolAddress((void**)&p_ff, g_ff);

    // 1) R (8x8)
    compute_R_kernel<<<1, 64>>>(W_ct1, b_ct1, W_ct2, b_ct2, Mm);
    // 2) ptm + u
    ptm_kernel<<<BSn, 256>>>(h, W_ptm, b_ptm);
    // 3) QKV projections
    dim3 gqkv(Hn/128, BSn/128);
    gemm_nt<<<gqkv, 256>>>(h, Wq, bq, nullptr, p_q, Hn, Hn, 0);
    gemm_nt<<<gqkv, 256>>>(h, Wk, bk, nullptr, p_k, Hn, Hn, 0);
    gemm_nt<<<gqkv, 256>>>(h, Wv, bv, nullptr, p_v, Hn, Hn, 0);
    // 4) attention (flash, fused bias)
    size_t smem = (size_t)(3*64*65 + 64*64 + 64*8 + 64*8 + 64) * sizeof(float);
    cudaFuncSetAttribute(attn_kernel, cudaFuncAttributeMaxDynamicSharedMemorySize, (int)smem);
    attn_kernel<<<dim3(Sn/64, NHn, Bn), 256, smem>>>(amask, bscale);
    // 5) residual + LN
    ln_kernel<<<BSn, 256>>>(h, ln_g, ln_b);
    // 6) FFN1 + GELU
    gemm_nt<<<dim3(In/128, BSn/128), 256>>>(p_x, Wf1, bf1, nullptr, p_ff, In, Hn, 1);
    // 7) FFN2 + residual -> out
    gemm_nt<<<dim3(Hn/128, BSn/128), 256>>>(p_ff, Wf2, bf2, p_x, out, Hn, In, 2);
}